// round 12
// baseline (speedup 1.0000x reference)
#include <cuda_runtime.h>
#include <cstdint>

// S3FD anchor assignment: spatial binning (atomic-free counting sort) + fused main.
//   k_hist:    4 anchors/thread: cell id (16x16 grid of 64px cells, by center),
//              per-block smem histogram -> g_blockhist[cell][block]
//   k_phase2:  blocks [0,NCELL): per-cell exclusive scan of block counts;
//              blocks [NCELL,2N): per-cell GT lists (order-preserving ballot
//              compaction -> increasing GT order = reference first-max tie-break)
//              + zero g_top. Last block (ticket): offsets + LPT-ordered chunk
//              worklist (cells with more GTs first).
//   k_scatter: 4 anchors/thread: smem cursors -> scatter 4B anchor idx only.
//   k_main:    static LPT grid, 4 anchors/thread. BRANCHLESS inner loop:
//              unconditional exact __fdiv_rn (0/denom==0 for non-overlap pairs;
//              the divide ran ~warp-coherently anyway), predicated argmax
//              (strict >, first-max ties), ONE rare branch for the atomic gates:
//              per-GT ungated MAX slot (fake-seeded from global: monotone-max,
//              safe) + 0.1-gated 3-slot cascade (not seeded).
//              Last-finishing block (ticket): resolve forced claims into out.
// Output dtype float32 (small ints as floats). All exact comparisons use
// __f*_rn-rounded iou: bit-identical to the float32 reference. The 0.1 gate is
// exact: cascade entries are only consumed under a vals>0.1 condition, and >0.5
// counting is unaffected since >0.5 entries form a prefix of the sorted row.

#define TPB 256
#define APT 4
#define CHUNK 1024             // = TPB*APT
#define MAXM 256               // >= n_gt (200)
#define MAXN (1 << 20)         // >= n_anchor (500000)
#define NB_MAX (MAXN / CHUNK)
#define NCELL 256
#define GRIDW 16
#define CELL_PX 64.0f
#define EXPAND 65.0f           // 64 max anchor half-extent + 1px rounding slack

__device__ unsigned char g_cellid[MAXN];
__device__ int g_blockhist[NCELL * NB_MAX];
__device__ int g_celltotal[NCELL];
__device__ int g_offs[NCELL];
__device__ int g_nwork;
__device__ int4 g_work[NCELL + MAXN / CHUNK + 2];
__device__ int g_binned[MAXN];
__device__ int g_gtcnt[NCELL];
__device__ int g_gtlist[NCELL * MAXM];
// Per-gt: [4g+0] = ungated max slot, [4g+1..3] = 0.1-gated top-3 cascade.
__device__ unsigned long long g_top[MAXM * 4];
__device__ unsigned g_tick1, g_tick2;

// Lock-free top-3 insert: slots monotone non-decreasing under atomicMax; the
// displaced minimum cascades down. Real keys are globally unique (low = ~idx).
__device__ __forceinline__ void cascade_insert(unsigned long long* s, unsigned long long v) {
#pragma unroll
    for (int i = 0; i < 3; i++) {
        unsigned long long old = atomicMax(&s[i], v);
        v = old < v ? old : v;
        if (v == 0ull) return;
    }
}

__device__ __forceinline__ int cell_of(float4 a) {
    int cx = min(GRIDW - 1, max(0, (int)((a.x + a.z) * (0.5f / CELL_PX))));
    int cy = min(GRIDW - 1, max(0, (int)((a.y + a.w) * (0.5f / CELL_PX))));
    return cy * GRIDW + cx;
}

__global__ void __launch_bounds__(TPB) k_hist(const float4* __restrict__ anc, int n) {
    __shared__ int h[NCELL];
    const int t = threadIdx.x, b = blockIdx.x;
    h[t] = 0;
    __syncthreads();
    const int base = b * CHUNK;
#pragma unroll
    for (int k = 0; k < APT; k++) {
        int i = base + k * TPB + t;
        if (i < n) {
            int c = cell_of(anc[i]);
            g_cellid[i] = (unsigned char)c;
            atomicAdd(&h[c], 1);
        }
    }
    __syncthreads();
    g_blockhist[t * gridDim.x + b] = h[t];
}

__global__ void __launch_bounds__(TPB) k_phase2(int nb, const float4* __restrict__ gts, int m) {
    __shared__ int sh[TPB];
    __shared__ int sh2[TPB];
    const int t = threadIdx.x;
    if (blockIdx.x < NCELL) {
        const int c = blockIdx.x;
        const int per = (nb + TPB - 1) / TPB;
        int* row = &g_blockhist[c * nb];
        int s = 0;
        for (int k = 0; k < per; k++) {
            int idx = t * per + k;
            if (idx < nb) s += row[idx];
        }
        sh[t] = s;
        __syncthreads();
        for (int d = 1; d < TPB; d <<= 1) {
            int x = (t >= d) ? sh[t - d] : 0; __syncthreads();
            sh[t] += x; __syncthreads();
        }
        int run = sh[t] - s;
        for (int k = 0; k < per; k++) {
            int idx = t * per + k;
            if (idx < nb) { int v = row[idx]; row[idx] = run; run += v; }
        }
        if (t == TPB - 1) g_celltotal[c] = sh[t];
    } else {
        const int c = blockIdx.x - NCELL;
        if (c < 4) {
            int i = c * TPB + t;
            if (i < MAXM * 4) g_top[i] = 0ull;
        }
        float cx0 = (c & (GRIDW - 1)) * CELL_PX - EXPAND;
        float cx1 = (c & (GRIDW - 1)) * CELL_PX + CELL_PX + EXPAND;
        float cy0 = (c >> 4) * CELL_PX - EXPAND;
        float cy1 = (c >> 4) * CELL_PX + CELL_PX + EXPAND;
        bool p = false;
        if (t < m) {
            float4 G = gts[t];
            p = (G.x <= cx1 && G.z >= cx0 && G.y <= cy1 && G.w >= cy0);
        }
        unsigned bl = __ballot_sync(0xffffffffu, p);
        int wid = t >> 5, lane = t & 31;
        int rank = __popc(bl & ((1u << lane) - 1u));
        if (lane == 0) sh[wid] = __popc(bl);
        __syncthreads();
        int base = 0;
        for (int w = 0; w < wid; w++) base += sh[w];
        if (p) g_gtlist[c * MAXM + base + rank] = t;
        if (t == 0) {
            int tot = 0;
            for (int w = 0; w < TPB / 32; w++) tot += sh[w];
            g_gtcnt[c] = tot;
        }
    }

    // ---- ticket: last block builds offsets + LPT-ordered worklist ----
    __syncthreads();
    __threadfence();
    __shared__ unsigned old;
    if (t == 0) old = atomicAdd(&g_tick1, 1u);
    __syncthreads();
    if (old == gridDim.x - 1) {
        // Bin offsets (cell-index order; scatter layout is order-independent).
        int v = __ldcg(&g_celltotal[t]);
        sh[t] = v; __syncthreads();
        for (int d = 1; d < NCELL; d <<= 1) {
            int x = (t >= d) ? sh[t - d] : 0; __syncthreads();
            sh[t] += x; __syncthreads();
        }
        int excl = sh[t] - v;
        g_offs[t] = excl;
        // LPT rank: cells with more GTs first (ties by cell index).
        int mygt = __ldcg(&g_gtcnt[t]);
        sh2[t] = mygt;
        __syncthreads();
        int rank = 0;
        for (int u = 0; u < NCELL; u++) {
            int gu = sh2[u];
            if (gu > mygt || (gu == mygt && u < t)) rank++;
        }
        __syncthreads();
        // Chunk-count prefix over LPT order.
        int ch = (v + CHUNK - 1) / CHUNK;
        sh[rank] = ch;
        __syncthreads();
        int cv = sh[t];
        for (int d = 1; d < NCELL; d <<= 1) {
            int x = (t >= d) ? sh[t - d] : 0; __syncthreads();
            sh[t] += x; __syncthreads();
        }
        if (t == NCELL - 1) g_nwork = sh[t];
        __syncthreads();
        sh2[t] = sh[t] - cv;            // exclusive prefix at LPT position t
        __syncthreads();
        int chexcl = sh2[rank];
        for (int k = 0; k < ch; k++)
            g_work[chexcl + k] = make_int4(t, excl + k * CHUNK, min(CHUNK, v - k * CHUNK), 0);
        if (t == 0) g_tick1 = 0;
    }
}

__global__ void __launch_bounds__(TPB) k_scatter(int n, int nb) {
    __shared__ int cur[NCELL];
    const int t = threadIdx.x, b = blockIdx.x;
    cur[t] = g_offs[t] + g_blockhist[t * nb + b];
    __syncthreads();
    const int base = b * CHUNK;
#pragma unroll
    for (int k = 0; k < APT; k++) {
        int i = base + k * TPB + t;
        if (i < n) {
            int c = g_cellid[i];
            int pos = atomicAdd(&cur[c], 1);
            g_binned[pos] = i;
        }
    }
}

__global__ void __launch_bounds__(TPB) k_main(
    const float4* __restrict__ anc, const float4* __restrict__ gts,
    int m, float* __restrict__ out, unsigned long long* __restrict__ gtop)
{
    __shared__ float4 sgc[MAXM];
    __shared__ float sga[MAXM];
    __shared__ int sgi[MAXM];
    __shared__ unsigned long long smax[MAXM];       // per-gt ungated max (local)
    __shared__ unsigned long long scas[MAXM * 3];   // per-gt 0.1-gated top-3 (local)

    const int tid = threadIdx.x;
    const bool active_blk = blockIdx.x < g_nwork;
    if (active_blk) {
        int4 w = g_work[blockIdx.x];
        const int cell = w.x, astart = w.y, alen = w.z;
        const int cnt = g_gtcnt[cell];

        // Prologue. smax is seeded from global with a FAKE key (hi<<32|0):
        // pure monotone max -> raising the local gate is always safe, and merge
        // skips low==0. The cascade is NOT seeded (seeding can evict real keys).
        if (tid < cnt) {
            int gi = g_gtlist[cell * MAXM + tid];
            float4 G = gts[gi];
            sgc[tid] = G;
            sga[tid] = __fmul_rn(__fsub_rn(G.z, G.x), __fsub_rn(G.w, G.y));
            sgi[tid] = gi;
            smax[tid] = __ldcg(&gtop[gi * 4 + 0]) & 0xFFFFFFFF00000000ull;
        }
        for (int i = tid; i < cnt * 3; i += TPB) scas[i] = 0ull;
        __syncthreads();

        float ax1[APT], ay1[APT], ax2[APT], ay2[APT], aar[APT], best[APT];
        int bc[APT], aidx[APT];
        bool act[APT];
#pragma unroll
        for (int j = 0; j < APT; j++) {
            int p = tid + j * TPB;
            act[j] = p < alen;
            aidx[j] = act[j] ? g_binned[astart + p] : 0;
            float4 a = act[j] ? anc[aidx[j]] : make_float4(4e9f, 4e9f, 4e9f, 4e9f);
            ax1[j] = a.x; ay1[j] = a.y; ax2[j] = a.z; ay2[j] = a.w;
            aar[j] = __fmul_rn(__fsub_rn(a.z, a.x), __fsub_rn(a.w, a.y));
            best[j] = 0.f;   // all-zero row -> ref argmax 0
            bc[j] = 0;
        }

        // Monotone hi-word stale reads are safe lower bounds for both gates.
        const unsigned* smax_hi = (const unsigned*)smax;
        const unsigned* scas_hi = (const unsigned*)scas;
        const unsigned TENTH = 0x3DCCCCCDu;   // __float_as_uint(0.1f)

        for (int c = 0; c < cnt; c++) {
            float4 G = sgc[c];
            float ga = sga[c];
            unsigned mxh = smax_hi[c * 2 + 1];
            unsigned mh2 = scas_hi[(c * 3 + 2) * 2 + 1];
#pragma unroll
            for (int j = 0; j < APT; j++) {
                float ltx = fmaxf(ax1[j], G.x), lty = fmaxf(ay1[j], G.y);
                float rbx = fminf(ax2[j], G.z), rby = fminf(ay2[j], G.w);
                float wd = fmaxf(__fsub_rn(rbx, ltx), 0.f);
                float ht = fmaxf(__fsub_rn(rby, lty), 0.f);
                float inter = __fmul_rn(wd, ht);
                float denom = __fsub_rn(__fadd_rn(aar[j], ga), inter);
                // Unconditional exact divide: 0/denom == 0 for non-overlap pairs
                // (denom > 0 always: real boxes have positive area; sentinel
                // lanes have aar==0 but ga>0). Branchless argmax below.
                float iou = __fdiv_rn(inter, denom);   // IEEE rn = reference
                bool better = iou > best[j];           // strict > keeps first max
                best[j] = better ? iou : best[j];
                bc[j]   = better ? c   : bc[j];
                unsigned ib = __float_as_uint(iou);
                // Single rare branch: only when this pair can raise a gate.
                if (inter > 0.f && (ib >= mxh || (ib > TENTH && ib >= mh2))) {
                    unsigned long long key =
                        ((unsigned long long)ib << 32) | (unsigned)(~(unsigned)aidx[j]);
                    if (ib >= mxh) {
                        atomicMax(&smax[c], key);
                        mxh = smax_hi[c * 2 + 1];
                    }
                    if (ib > TENTH && ib >= mh2) {     // iou > 0.1 gate
                        cascade_insert(&scas[c * 3], key);
                        mh2 = scas_hi[(c * 3 + 2) * 2 + 1];
                    }
                }
            }
        }

#pragma unroll
        for (int j = 0; j < APT; j++) {
            if (act[j]) {
                float r = -2.0f;
                if (best[j] < 0.3f) r = -1.0f;
                if (best[j] > 0.5f) r = (float)sgi[bc[j]];
                out[aidx[j]] = r;
            }
        }

        // Merge real (low!=0) local slots into global tables.
        __syncthreads();
        const unsigned* gtop_hi = (const unsigned*)gtop;
        for (int i = tid; i < cnt * 4; i += TPB) {
            int g = i >> 2, slot = i & 3;
            int orig = sgi[g];
            unsigned long long v = (slot == 0) ? smax[g] : scas[g * 3 + slot - 1];
            if ((unsigned)v == 0u) continue;           // empty or seed fake
            if (slot == 0) {
                atomicMax(&gtop[orig * 4], v);
            } else {
                unsigned gm = gtop_hi[(orig * 4 + 3) * 2 + 1];
                if ((unsigned)(v >> 32) >= gm) cascade_insert(&gtop[orig * 4 + 1], v);
            }
        }
    }

    // ---- ticket: last-finishing block resolves forced claims ----
    __syncthreads();
    __threadfence();
    __shared__ unsigned old;
    if (tid == 0) old = atomicAdd(&g_tick2, 1u);
    __syncthreads();
    if (old == gridDim.x - 1) {
        // Overlay resolve arrays on dead smem.
        int* ea = (int*)scas;                 // [MAXM*3]
        int* eg = ((int*)scas) + MAXM * 3;    // [MAXM*3]
        int* win = (int*)sgc;                 // [MAXM*3]
        __shared__ int rcnt;
        if (tid == 0) rcnt = 0;
        __syncthreads();
        if (tid < m) {
            unsigned long long s0 = __ldcg(&gtop[tid * 4 + 0]);   // overall max
            unsigned long long s1 = __ldcg(&gtop[tid * 4 + 2]);   // vals[1] (>0.1)
            unsigned long long s2 = __ldcg(&gtop[tid * 4 + 3]);   // vals[2] (>0.1)
            float v0 = __uint_as_float((unsigned)(s0 >> 32));
            float v1 = __uint_as_float((unsigned)(s1 >> 32));
            float v2 = __uint_as_float((unsigned)(s2 >> 32));
            int npos = (v0 > 0.5f) + (v1 > 0.5f) + (v2 > 0.5f);
            bool low = npos < 3;
            // k==0 always claims; empty slot = all-zero row -> ref rank0 = anchor 0.
            int a0 = s0 ? (int)(~(unsigned)s0) : 0;
            int e = atomicAdd(&rcnt, 1); ea[e] = a0; eg[e] = tid;
            if (low) {
                if (s1) { e = atomicAdd(&rcnt, 1); ea[e] = (int)(~(unsigned)s1); eg[e] = tid; }
                if (s2) { e = atomicAdd(&rcnt, 1); ea[e] = (int)(~(unsigned)s2); eg[e] = tid; }
            }
        }
        __syncthreads();
        const int E = rcnt;
        for (int j = tid; j < E; j += TPB) win[j] = -1;
        __syncthreads();
        // winner per anchor = max claiming gt (reference scatter-max), keyed on
        // the first list occurrence of each anchor.
        for (int j = tid; j < E; j += TPB) {
            int aj = ea[j];
            int rep = j;
            for (int k = 0; k < j; k++)
                if (ea[k] == aj) { rep = k; break; }
            atomicMax(&win[rep], eg[j]);
        }
        __syncthreads();
        for (int j = tid; j < E; j += TPB)
            if (win[j] >= 0) out[ea[j]] = (float)win[j];
        if (tid == 0) g_tick2 = 0;
    }
}

extern "C" void kernel_launch(void* const* d_in, const int* in_sizes, int n_in,
                              void* d_out, int out_size)
{
    const float4* anc = (const float4*)d_in[0];
    const float4* gts = (const float4*)d_in[1];
    int n = in_sizes[0] / 4;
    int m = in_sizes[1] / 4;
    float* out = (float*)d_out;

    void* ptop = nullptr;
    cudaGetSymbolAddress(&ptop, g_top);

    int nb = (n + CHUNK - 1) / CHUNK;
    k_hist<<<nb, TPB>>>(anc, n);
    k_phase2<<<NCELL * 2, TPB>>>(nb, gts, m);
    k_scatter<<<nb, TPB>>>(n, nb);
    int mblocks = NCELL + (n + CHUNK - 1) / CHUNK;
    k_main<<<mblocks, TPB>>>(anc, gts, m, out, (unsigned long long*)ptop);
}

// round 13
// speedup vs baseline: 1.1586x; 1.1586x over previous
#include <cuda_runtime.h>
#include <cstdint>

// S3FD anchor assignment: spatial binning (atomic-free counting sort) + fused main.
// == R10 kernel (best measured k_main) with ONE change: __launch_bounds__(TPB,5)
//    on k_main to force regs<=51 -> 5 blocks/SM (62.5% occupancy ceiling).
//   k_hist:    4 anchors/thread: cell id (16x16 grid of 64px cells, by center),
//              per-block smem histogram -> g_blockhist[cell][block]
//   k_phase2:  blocks [0,NCELL): per-cell exclusive scan of block counts;
//              blocks [NCELL,2N): per-cell GT lists (order-preserving ballot
//              compaction -> increasing GT order = reference first-max tie-break)
//              + zero g_top. Last block (ticket): offsets + LPT-ordered chunk
//              worklist (cells with more GTs first).
//   k_scatter: 4 anchors/thread: smem cursors -> scatter 4B anchor idx only.
//   k_main:    static LPT grid, 4 anchors/thread: IoU vs cell's GT list,
//              per-lane-predicated divide (inter>0), argmax (exact __fdiv_rn,
//              strict >, first-max ties), per-GT ungated MAX slot (fake-seeded
//              from global: monotone-max, safe) + 0.1-gated 3-slot cascade
//              (not seeded). Last-finishing block (ticket): resolve claims.
// Output dtype float32 (small ints as floats). All exact comparisons use
// __f*_rn-rounded iou: bit-identical to the float32 reference. The 0.1 gate is
// exact: cascade entries are only consumed under a vals>0.1 condition, and >0.5
// counting is unaffected since >0.5 entries form a prefix of the sorted row.

#define TPB 256
#define APT 4
#define CHUNK 1024             // = TPB*APT
#define MAXM 256               // >= n_gt (200)
#define MAXN (1 << 20)         // >= n_anchor (500000)
#define NB_MAX (MAXN / CHUNK)
#define NCELL 256
#define GRIDW 16
#define CELL_PX 64.0f
#define EXPAND 65.0f           // 64 max anchor half-extent + 1px rounding slack

__device__ unsigned char g_cellid[MAXN];
__device__ int g_blockhist[NCELL * NB_MAX];
__device__ int g_celltotal[NCELL];
__device__ int g_offs[NCELL];
__device__ int g_nwork;
__device__ int4 g_work[NCELL + MAXN / CHUNK + 2];
__device__ int g_binned[MAXN];
__device__ int g_gtcnt[NCELL];
__device__ int g_gtlist[NCELL * MAXM];
// Per-gt: [4g+0] = ungated max slot, [4g+1..3] = 0.1-gated top-3 cascade.
__device__ unsigned long long g_top[MAXM * 4];
__device__ unsigned g_tick1, g_tick2;

// Lock-free top-3 insert: slots monotone non-decreasing under atomicMax; the
// displaced minimum cascades down. Real keys are globally unique (low = ~idx).
__device__ __forceinline__ void cascade_insert(unsigned long long* s, unsigned long long v) {
#pragma unroll
    for (int i = 0; i < 3; i++) {
        unsigned long long old = atomicMax(&s[i], v);
        v = old < v ? old : v;
        if (v == 0ull) return;
    }
}

__device__ __forceinline__ int cell_of(float4 a) {
    int cx = min(GRIDW - 1, max(0, (int)((a.x + a.z) * (0.5f / CELL_PX))));
    int cy = min(GRIDW - 1, max(0, (int)((a.y + a.w) * (0.5f / CELL_PX))));
    return cy * GRIDW + cx;
}

__global__ void __launch_bounds__(TPB) k_hist(const float4* __restrict__ anc, int n) {
    __shared__ int h[NCELL];
    const int t = threadIdx.x, b = blockIdx.x;
    h[t] = 0;
    __syncthreads();
    const int base = b * CHUNK;
#pragma unroll
    for (int k = 0; k < APT; k++) {
        int i = base + k * TPB + t;
        if (i < n) {
            int c = cell_of(anc[i]);
            g_cellid[i] = (unsigned char)c;
            atomicAdd(&h[c], 1);
        }
    }
    __syncthreads();
    g_blockhist[t * gridDim.x + b] = h[t];
}

__global__ void __launch_bounds__(TPB) k_phase2(int nb, const float4* __restrict__ gts, int m) {
    __shared__ int sh[TPB];
    __shared__ int sh2[TPB];
    const int t = threadIdx.x;
    if (blockIdx.x < NCELL) {
        const int c = blockIdx.x;
        const int per = (nb + TPB - 1) / TPB;
        int* row = &g_blockhist[c * nb];
        int s = 0;
        for (int k = 0; k < per; k++) {
            int idx = t * per + k;
            if (idx < nb) s += row[idx];
        }
        sh[t] = s;
        __syncthreads();
        for (int d = 1; d < TPB; d <<= 1) {
            int x = (t >= d) ? sh[t - d] : 0; __syncthreads();
            sh[t] += x; __syncthreads();
        }
        int run = sh[t] - s;
        for (int k = 0; k < per; k++) {
            int idx = t * per + k;
            if (idx < nb) { int v = row[idx]; row[idx] = run; run += v; }
        }
        if (t == TPB - 1) g_celltotal[c] = sh[t];
    } else {
        const int c = blockIdx.x - NCELL;
        if (c < 4) {
            int i = c * TPB + t;
            if (i < MAXM * 4) g_top[i] = 0ull;
        }
        float cx0 = (c & (GRIDW - 1)) * CELL_PX - EXPAND;
        float cx1 = (c & (GRIDW - 1)) * CELL_PX + CELL_PX + EXPAND;
        float cy0 = (c >> 4) * CELL_PX - EXPAND;
        float cy1 = (c >> 4) * CELL_PX + CELL_PX + EXPAND;
        bool p = false;
        if (t < m) {
            float4 G = gts[t];
            p = (G.x <= cx1 && G.z >= cx0 && G.y <= cy1 && G.w >= cy0);
        }
        unsigned bl = __ballot_sync(0xffffffffu, p);
        int wid = t >> 5, lane = t & 31;
        int rank = __popc(bl & ((1u << lane) - 1u));
        if (lane == 0) sh[wid] = __popc(bl);
        __syncthreads();
        int base = 0;
        for (int w = 0; w < wid; w++) base += sh[w];
        if (p) g_gtlist[c * MAXM + base + rank] = t;
        if (t == 0) {
            int tot = 0;
            for (int w = 0; w < TPB / 32; w++) tot += sh[w];
            g_gtcnt[c] = tot;
        }
    }

    // ---- ticket: last block builds offsets + LPT-ordered worklist ----
    __syncthreads();
    __threadfence();
    __shared__ unsigned old;
    if (t == 0) old = atomicAdd(&g_tick1, 1u);
    __syncthreads();
    if (old == gridDim.x - 1) {
        // Bin offsets (cell-index order; scatter layout is order-independent).
        int v = __ldcg(&g_celltotal[t]);
        sh[t] = v; __syncthreads();
        for (int d = 1; d < NCELL; d <<= 1) {
            int x = (t >= d) ? sh[t - d] : 0; __syncthreads();
            sh[t] += x; __syncthreads();
        }
        int excl = sh[t] - v;
        g_offs[t] = excl;
        // LPT rank: cells with more GTs first (ties by cell index).
        int mygt = __ldcg(&g_gtcnt[t]);
        sh2[t] = mygt;
        __syncthreads();
        int rank = 0;
        for (int u = 0; u < NCELL; u++) {
            int gu = sh2[u];
            if (gu > mygt || (gu == mygt && u < t)) rank++;
        }
        __syncthreads();
        // Chunk-count prefix over LPT order.
        int ch = (v + CHUNK - 1) / CHUNK;
        sh[rank] = ch;
        __syncthreads();
        int cv = sh[t];
        for (int d = 1; d < NCELL; d <<= 1) {
            int x = (t >= d) ? sh[t - d] : 0; __syncthreads();
            sh[t] += x; __syncthreads();
        }
        if (t == NCELL - 1) g_nwork = sh[t];
        __syncthreads();
        sh2[t] = sh[t] - cv;            // exclusive prefix at LPT position t
        __syncthreads();
        int chexcl = sh2[rank];
        for (int k = 0; k < ch; k++)
            g_work[chexcl + k] = make_int4(t, excl + k * CHUNK, min(CHUNK, v - k * CHUNK), 0);
        if (t == 0) g_tick1 = 0;
    }
}

__global__ void __launch_bounds__(TPB) k_scatter(int n, int nb) {
    __shared__ int cur[NCELL];
    const int t = threadIdx.x, b = blockIdx.x;
    cur[t] = g_offs[t] + g_blockhist[t * nb + b];
    __syncthreads();
    const int base = b * CHUNK;
#pragma unroll
    for (int k = 0; k < APT; k++) {
        int i = base + k * TPB + t;
        if (i < n) {
            int c = g_cellid[i];
            int pos = atomicAdd(&cur[c], 1);
            g_binned[pos] = i;
        }
    }
}

__global__ void __launch_bounds__(TPB, 5) k_main(
    const float4* __restrict__ anc, const float4* __restrict__ gts,
    int m, float* __restrict__ out, unsigned long long* __restrict__ gtop)
{
    __shared__ float4 sgc[MAXM];
    __shared__ float sga[MAXM];
    __shared__ int sgi[MAXM];
    __shared__ unsigned long long smax[MAXM];       // per-gt ungated max (local)
    __shared__ unsigned long long scas[MAXM * 3];   // per-gt 0.1-gated top-3 (local)

    const int tid = threadIdx.x;
    const bool active_blk = blockIdx.x < g_nwork;
    if (active_blk) {
        int4 w = g_work[blockIdx.x];
        const int cell = w.x, astart = w.y, alen = w.z;
        const int cnt = g_gtcnt[cell];

        // Prologue. smax is seeded from global with a FAKE key (hi<<32|0):
        // pure monotone max -> raising the local gate is always safe, and merge
        // skips low==0. The cascade is NOT seeded (seeding can evict real keys).
        if (tid < cnt) {
            int gi = g_gtlist[cell * MAXM + tid];
            float4 G = gts[gi];
            sgc[tid] = G;
            sga[tid] = __fmul_rn(__fsub_rn(G.z, G.x), __fsub_rn(G.w, G.y));
            sgi[tid] = gi;
            smax[tid] = __ldcg(&gtop[gi * 4 + 0]) & 0xFFFFFFFF00000000ull;
        }
        for (int i = tid; i < cnt * 3; i += TPB) scas[i] = 0ull;
        __syncthreads();

        float ax1[APT], ay1[APT], ax2[APT], ay2[APT], aar[APT], best[APT];
        int bc[APT], aidx[APT];
        bool act[APT];
#pragma unroll
        for (int j = 0; j < APT; j++) {
            int p = tid + j * TPB;
            act[j] = p < alen;
            aidx[j] = act[j] ? g_binned[astart + p] : 0;
            float4 a = act[j] ? anc[aidx[j]] : make_float4(4e9f, 4e9f, 4e9f, 4e9f);
            ax1[j] = a.x; ay1[j] = a.y; ax2[j] = a.z; ay2[j] = a.w;
            aar[j] = __fmul_rn(__fsub_rn(a.z, a.x), __fsub_rn(a.w, a.y));
            best[j] = 0.f;   // all-zero row -> ref argmax 0
            bc[j] = 0;
        }

        // Monotone hi-word stale reads are safe lower bounds for both gates.
        const unsigned* smax_hi = (const unsigned*)smax;
        const unsigned* scas_hi = (const unsigned*)scas;
        const unsigned TENTH = 0x3DCCCCCDu;   // __float_as_uint(0.1f)

        for (int c = 0; c < cnt; c++) {
            float4 G = sgc[c];
            float ga = sga[c];
            unsigned mxh = smax_hi[c * 2 + 1];
            unsigned mh2 = scas_hi[(c * 3 + 2) * 2 + 1];
#pragma unroll
            for (int j = 0; j < APT; j++) {
                float ltx = fmaxf(ax1[j], G.x), lty = fmaxf(ay1[j], G.y);
                float rbx = fminf(ax2[j], G.z), rby = fminf(ay2[j], G.w);
                float wd = fmaxf(__fsub_rn(rbx, ltx), 0.f);
                float ht = fmaxf(__fsub_rn(rby, lty), 0.f);
                float inter = __fmul_rn(wd, ht);
                if (inter > 0.f) {
                    float denom = __fsub_rn(__fadd_rn(aar[j], ga), inter);
                    float iou = __fdiv_rn(inter, denom);   // IEEE rn = reference
                    if (iou > best[j]) { best[j] = iou; bc[j] = c; }
                    unsigned ib = __float_as_uint(iou);
                    if (ib >= mxh) {
                        unsigned long long key =
                            ((unsigned long long)ib << 32) | (unsigned)(~(unsigned)aidx[j]);
                        atomicMax(&smax[c], key);
                        mxh = smax_hi[c * 2 + 1];
                    }
                    if (ib > TENTH && ib >= mh2) {         // iou > 0.1 gate
                        unsigned long long key =
                            ((unsigned long long)ib << 32) | (unsigned)(~(unsigned)aidx[j]);
                        cascade_insert(&scas[c * 3], key);
                        mh2 = scas_hi[(c * 3 + 2) * 2 + 1];
                    }
                }
            }
        }

#pragma unroll
        for (int j = 0; j < APT; j++) {
            if (act[j]) {
                float r = -2.0f;
                if (best[j] < 0.3f) r = -1.0f;
                if (best[j] > 0.5f) r = (float)sgi[bc[j]];
                out[aidx[j]] = r;
            }
        }

        // Merge real (low!=0) local slots into global tables.
        __syncthreads();
        const unsigned* gtop_hi = (const unsigned*)gtop;
        for (int i = tid; i < cnt * 4; i += TPB) {
            int g = i >> 2, slot = i & 3;
            int orig = sgi[g];
            unsigned long long v = (slot == 0) ? smax[g] : scas[g * 3 + slot - 1];
            if ((unsigned)v == 0u) continue;           // empty or seed fake
            if (slot == 0) {
                atomicMax(&gtop[orig * 4], v);
            } else {
                unsigned gm = gtop_hi[(orig * 4 + 3) * 2 + 1];
                if ((unsigned)(v >> 32) >= gm) cascade_insert(&gtop[orig * 4 + 1], v);
            }
        }
    }

    // ---- ticket: last-finishing block resolves forced claims ----
    __syncthreads();
    __threadfence();
    __shared__ unsigned old;
    if (tid == 0) old = atomicAdd(&g_tick2, 1u);
    __syncthreads();
    if (old == gridDim.x - 1) {
        // Overlay resolve arrays on dead smem.
        int* ea = (int*)scas;                 // [MAXM*3]
        int* eg = ((int*)scas) + MAXM * 3;    // [MAXM*3]
        int* win = (int*)sgc;                 // [MAXM*3]
        __shared__ int rcnt;
        if (tid == 0) rcnt = 0;
        __syncthreads();
        if (tid < m) {
            unsigned long long s0 = __ldcg(&gtop[tid * 4 + 0]);   // overall max
            unsigned long long s1 = __ldcg(&gtop[tid * 4 + 2]);   // vals[1] (>0.1)
            unsigned long long s2 = __ldcg(&gtop[tid * 4 + 3]);   // vals[2] (>0.1)
            float v0 = __uint_as_float((unsigned)(s0 >> 32));
            float v1 = __uint_as_float((unsigned)(s1 >> 32));
            float v2 = __uint_as_float((unsigned)(s2 >> 32));
            int npos = (v0 > 0.5f) + (v1 > 0.5f) + (v2 > 0.5f);
            bool low = npos < 3;
            // k==0 always claims; empty slot = all-zero row -> ref rank0 = anchor 0.
            int a0 = s0 ? (int)(~(unsigned)s0) : 0;
            int e = atomicAdd(&rcnt, 1); ea[e] = a0; eg[e] = tid;
            if (low) {
                if (s1) { e = atomicAdd(&rcnt, 1); ea[e] = (int)(~(unsigned)s1); eg[e] = tid; }
                if (s2) { e = atomicAdd(&rcnt, 1); ea[e] = (int)(~(unsigned)s2); eg[e] = tid; }
            }
        }
        __syncthreads();
        const int E = rcnt;
        for (int j = tid; j < E; j += TPB) win[j] = -1;
        __syncthreads();
        // winner per anchor = max claiming gt (reference scatter-max), keyed on
        // the first list occurrence of each anchor.
        for (int j = tid; j < E; j += TPB) {
            int aj = ea[j];
            int rep = j;
            for (int k = 0; k < j; k++)
                if (ea[k] == aj) { rep = k; break; }
            atomicMax(&win[rep], eg[j]);
        }
        __syncthreads();
        for (int j = tid; j < E; j += TPB)
            if (win[j] >= 0) out[ea[j]] = (float)win[j];
        if (tid == 0) g_tick2 = 0;
    }
}

extern "C" void kernel_launch(void* const* d_in, const int* in_sizes, int n_in,
                              void* d_out, int out_size)
{
    const float4* anc = (const float4*)d_in[0];
    const float4* gts = (const float4*)d_in[1];
    int n = in_sizes[0] / 4;
    int m = in_sizes[1] / 4;
    float* out = (float*)d_out;

    void* ptop = nullptr;
    cudaGetSymbolAddress(&ptop, g_top);

    int nb = (n + CHUNK - 1) / CHUNK;
    k_hist<<<nb, TPB>>>(anc, n);
    k_phase2<<<NCELL * 2, TPB>>>(nb, gts, m);
    k_scatter<<<nb, TPB>>>(n, nb);
    int mblocks = NCELL + (n + CHUNK - 1) / CHUNK;
    k_main<<<mblocks, TPB>>>(anc, gts, m, out, (unsigned long long*)ptop);
}

// round 14
// speedup vs baseline: 1.1703x; 1.0101x over previous
#include <cuda_runtime.h>
#include <cstdint>

// S3FD anchor assignment: spatial binning (atomic-free counting sort) + fused main.
//   k_hist:    4 anchors/thread: cell id (16x16 grid of 64px cells, by center),
//              per-block smem histogram -> g_blockhist[cell][block]
//   k_phase2:  blocks [0,NCELL): per-cell exclusive scan of block counts;
//              blocks [NCELL,2N): per-cell GT lists (order-preserving ballot
//              compaction -> increasing GT order = reference first-max tie-break)
//              + zero g_top. Last block (ticket): offsets + EQUAL-PAIR chunk
//              worklist: chunk anchors s_c ~ (P_total/1480)/cnt_c rounded UP to
//              a multiple of 256 (no idle lanes), capped at 1024 -> per-block
//              work spread ~1.7x instead of 5.6x (fixes the drain imbalance
//              measured in R13: achieved occ 38% << theoretical 62%).
//   k_scatter: 4 anchors/thread: smem cursors -> scatter 4B anchor idx only.
//   k_main:    LPT-ordered chunks, templated unroll depth JM = ceil(alen/256):
//              IoU vs cell's GT list, per-lane-predicated divide (inter>0),
//              argmax (exact __fdiv_rn, strict >, first-max ties), per-GT
//              ungated MAX slot (fake-seeded from global: monotone-max, safe) +
//              0.1-gated 3-slot cascade (not seeded).
//              Last-finishing block (ticket): resolve forced claims into out.
// Output dtype float32 (small ints as floats). All exact comparisons use
// __f*_rn-rounded iou: bit-identical to the float32 reference. The 0.1 gate is
// exact: cascade entries are only consumed under a vals>0.1 condition, and >0.5
// counting is unaffected since >0.5 entries form a prefix of the sorted row.

#define TPB 256
#define APT 4
#define CHUNK 1024             // max anchors per chunk (= TPB*APT)
#define MAXM 256               // >= n_gt (200)
#define MAXN (1 << 20)         // >= n_anchor (500000)
#define NB_MAX (MAXN / CHUNK)
#define NCELL 256
#define GRIDW 16
#define CELL_PX 64.0f
#define EXPAND 65.0f           // 64 max anchor half-extent + 1px rounding slack
#define WCAP (NCELL + MAXN / 256 + 2)   // worst-case chunk count (min chunk 256)
#define TARGET_CHUNKS 1480     // ~2 waves of 740 slots, hardware-balanced

__device__ unsigned char g_cellid[MAXN];
__device__ int g_blockhist[NCELL * NB_MAX];
__device__ int g_celltotal[NCELL];
__device__ int g_offs[NCELL];
__device__ int g_nwork;
__device__ int4 g_work[WCAP];
__device__ int g_binned[MAXN];
__device__ int g_gtcnt[NCELL];
__device__ int g_gtlist[NCELL * MAXM];
// Per-gt: [4g+0] = ungated max slot, [4g+1..3] = 0.1-gated top-3 cascade.
__device__ unsigned long long g_top[MAXM * 4];
__device__ unsigned g_tick1, g_tick2;

// Lock-free top-3 insert: slots monotone non-decreasing under atomicMax; the
// displaced minimum cascades down. Real keys are globally unique (low = ~idx).
__device__ __forceinline__ void cascade_insert(unsigned long long* s, unsigned long long v) {
#pragma unroll
    for (int i = 0; i < 3; i++) {
        unsigned long long old = atomicMax(&s[i], v);
        v = old < v ? old : v;
        if (v == 0ull) return;
    }
}

__device__ __forceinline__ int cell_of(float4 a) {
    int cx = min(GRIDW - 1, max(0, (int)((a.x + a.z) * (0.5f / CELL_PX))));
    int cy = min(GRIDW - 1, max(0, (int)((a.y + a.w) * (0.5f / CELL_PX))));
    return cy * GRIDW + cx;
}

__global__ void __launch_bounds__(TPB) k_hist(const float4* __restrict__ anc, int n) {
    __shared__ int h[NCELL];
    const int t = threadIdx.x, b = blockIdx.x;
    h[t] = 0;
    __syncthreads();
    const int base = b * CHUNK;
#pragma unroll
    for (int k = 0; k < APT; k++) {
        int i = base + k * TPB + t;
        if (i < n) {
            int c = cell_of(anc[i]);
            g_cellid[i] = (unsigned char)c;
            atomicAdd(&h[c], 1);
        }
    }
    __syncthreads();
    g_blockhist[t * gridDim.x + b] = h[t];
}

__global__ void __launch_bounds__(TPB) k_phase2(int nb, const float4* __restrict__ gts, int m) {
    __shared__ int sh[TPB];
    __shared__ int sh2[TPB];
    const int t = threadIdx.x;
    if (blockIdx.x < NCELL) {
        const int c = blockIdx.x;
        const int per = (nb + TPB - 1) / TPB;
        int* row = &g_blockhist[c * nb];
        int s = 0;
        for (int k = 0; k < per; k++) {
            int idx = t * per + k;
            if (idx < nb) s += row[idx];
        }
        sh[t] = s;
        __syncthreads();
        for (int d = 1; d < TPB; d <<= 1) {
            int x = (t >= d) ? sh[t - d] : 0; __syncthreads();
            sh[t] += x; __syncthreads();
        }
        int run = sh[t] - s;
        for (int k = 0; k < per; k++) {
            int idx = t * per + k;
            if (idx < nb) { int v = row[idx]; row[idx] = run; run += v; }
        }
        if (t == TPB - 1) g_celltotal[c] = sh[t];
    } else {
        const int c = blockIdx.x - NCELL;
        if (c < 4) {
            int i = c * TPB + t;
            if (i < MAXM * 4) g_top[i] = 0ull;
        }
        float cx0 = (c & (GRIDW - 1)) * CELL_PX - EXPAND;
        float cx1 = (c & (GRIDW - 1)) * CELL_PX + CELL_PX + EXPAND;
        float cy0 = (c >> 4) * CELL_PX - EXPAND;
        float cy1 = (c >> 4) * CELL_PX + CELL_PX + EXPAND;
        bool p = false;
        if (t < m) {
            float4 G = gts[t];
            p = (G.x <= cx1 && G.z >= cx0 && G.y <= cy1 && G.w >= cy0);
        }
        unsigned bl = __ballot_sync(0xffffffffu, p);
        int wid = t >> 5, lane = t & 31;
        int rank = __popc(bl & ((1u << lane) - 1u));
        if (lane == 0) sh[wid] = __popc(bl);
        __syncthreads();
        int base = 0;
        for (int w = 0; w < wid; w++) base += sh[w];
        if (p) g_gtlist[c * MAXM + base + rank] = t;
        if (t == 0) {
            int tot = 0;
            for (int w = 0; w < TPB / 32; w++) tot += sh[w];
            g_gtcnt[c] = tot;
        }
    }

    // ---- ticket: last block builds offsets + equal-pair LPT worklist ----
    __syncthreads();
    __threadfence();
    __shared__ unsigned old;
    if (t == 0) old = atomicAdd(&g_tick1, 1u);
    __syncthreads();
    if (old == gridDim.x - 1) {
        int v = __ldcg(&g_celltotal[t]);
        int mygt = __ldcg(&g_gtcnt[t]);
        // Bin offsets (cell-index order; scatter layout is order-independent).
        sh[t] = v; __syncthreads();
        for (int d = 1; d < NCELL; d <<= 1) {
            int x = (t >= d) ? sh[t - d] : 0; __syncthreads();
            sh[t] += x; __syncthreads();
        }
        int excl = sh[t] - v;
        g_offs[t] = excl;
        // Total pair count P = sum v_c * cnt_c (Hillis scan; total at [255]).
        __syncthreads();
        sh2[t] = v * mygt; __syncthreads();
        for (int d = 1; d < NCELL; d <<= 1) {
            int x = (t >= d) ? sh2[t - d] : 0; __syncthreads();
            sh2[t] += x; __syncthreads();
        }
        const int P = sh2[NCELL - 1];
        __syncthreads();
        // Equal-pair chunk size: s ~ (P/TARGET)/cnt, rounded UP to x256, cap 1024.
        const int Tp = P / TARGET_CHUNKS + 1;
        int s = CHUNK;
        if (mygt > 0) {
            s = (Tp + mygt - 1) / mygt;
            s = (s + 255) & ~255;            // multiple of 256 -> no idle lanes
            if (s > CHUNK) s = CHUNK;
        }
        int ch = (s > 0) ? (v + s - 1) / s : 0;
        // LPT rank: cells with more GTs first (ties by cell index).
        sh2[t] = mygt; __syncthreads();
        int rank = 0;
        for (int u = 0; u < NCELL; u++) {
            int gu = sh2[u];
            if (gu > mygt || (gu == mygt && u < t)) rank++;
        }
        __syncthreads();
        // Chunk-count prefix over LPT order.
        sh[rank] = ch; __syncthreads();
        int cv = sh[t];
        for (int d = 1; d < NCELL; d <<= 1) {
            int x = (t >= d) ? sh[t - d] : 0; __syncthreads();
            sh[t] += x; __syncthreads();
        }
        if (t == NCELL - 1) g_nwork = sh[t];
        __syncthreads();
        sh2[t] = sh[t] - cv;            // exclusive prefix at LPT position t
        __syncthreads();
        int chexcl = sh2[rank];
        for (int k = 0; k < ch; k++)
            g_work[chexcl + k] = make_int4(t, excl + k * s, min(s, v - k * s), 0);
        if (t == 0) g_tick1 = 0;
    }
}

__global__ void __launch_bounds__(TPB) k_scatter(int n, int nb) {
    __shared__ int cur[NCELL];
    const int t = threadIdx.x, b = blockIdx.x;
    cur[t] = g_offs[t] + g_blockhist[t * nb + b];
    __syncthreads();
    const int base = b * CHUNK;
#pragma unroll
    for (int k = 0; k < APT; k++) {
        int i = base + k * TPB + t;
        if (i < n) {
            int c = g_cellid[i];
            int pos = atomicAdd(&cur[c], 1);
            g_binned[pos] = i;
        }
    }
}

// Mainloop templated on unroll depth JM = ceil(alen/TPB) in {1..4}: keeps
// per-anchor state in registers (static indexing) while matching chunk size.
template <int JM>
__device__ __forceinline__ void run_chunk(
    const float4* __restrict__ anc, float* __restrict__ out,
    int astart, int alen, int cnt, int tid,
    const float4* sgc, const float* sga, const int* sgi,
    unsigned long long* smax, unsigned long long* scas)
{
    float ax1[JM], ay1[JM], ax2[JM], ay2[JM], aar[JM], best[JM];
    int bc[JM], aidx[JM];
    bool act[JM];
#pragma unroll
    for (int j = 0; j < JM; j++) {
        int p = tid + j * TPB;
        act[j] = p < alen;
        aidx[j] = act[j] ? g_binned[astart + p] : 0;
        float4 a = act[j] ? anc[aidx[j]] : make_float4(4e9f, 4e9f, 4e9f, 4e9f);
        ax1[j] = a.x; ay1[j] = a.y; ax2[j] = a.z; ay2[j] = a.w;
        aar[j] = __fmul_rn(__fsub_rn(a.z, a.x), __fsub_rn(a.w, a.y));
        best[j] = 0.f;   // all-zero row -> ref argmax 0
        bc[j] = 0;
    }

    // Monotone hi-word stale reads are safe lower bounds for both gates.
    const unsigned* smax_hi = (const unsigned*)smax;
    const unsigned* scas_hi = (const unsigned*)scas;
    const unsigned TENTH = 0x3DCCCCCDu;   // __float_as_uint(0.1f)

    for (int c = 0; c < cnt; c++) {
        float4 G = sgc[c];
        float ga = sga[c];
        unsigned mxh = smax_hi[c * 2 + 1];
        unsigned mh2 = scas_hi[(c * 3 + 2) * 2 + 1];
#pragma unroll
        for (int j = 0; j < JM; j++) {
            float ltx = fmaxf(ax1[j], G.x), lty = fmaxf(ay1[j], G.y);
            float rbx = fminf(ax2[j], G.z), rby = fminf(ay2[j], G.w);
            float wd = fmaxf(__fsub_rn(rbx, ltx), 0.f);
            float ht = fmaxf(__fsub_rn(rby, lty), 0.f);
            float inter = __fmul_rn(wd, ht);
            if (inter > 0.f) {
                float denom = __fsub_rn(__fadd_rn(aar[j], ga), inter);
                float iou = __fdiv_rn(inter, denom);   // IEEE rn = reference
                if (iou > best[j]) { best[j] = iou; bc[j] = c; }
                unsigned ib = __float_as_uint(iou);
                if (ib >= mxh) {
                    unsigned long long key =
                        ((unsigned long long)ib << 32) | (unsigned)(~(unsigned)aidx[j]);
                    atomicMax(&smax[c], key);
                    mxh = smax_hi[c * 2 + 1];
                }
                if (ib > TENTH && ib >= mh2) {         // iou > 0.1 gate
                    unsigned long long key =
                        ((unsigned long long)ib << 32) | (unsigned)(~(unsigned)aidx[j]);
                    cascade_insert(&scas[c * 3], key);
                    mh2 = scas_hi[(c * 3 + 2) * 2 + 1];
                }
            }
        }
    }

#pragma unroll
    for (int j = 0; j < JM; j++) {
        if (act[j]) {
            float r = -2.0f;
            if (best[j] < 0.3f) r = -1.0f;
            if (best[j] > 0.5f) r = (float)sgi[bc[j]];
            out[aidx[j]] = r;
        }
    }
}

__global__ void __launch_bounds__(TPB, 5) k_main(
    const float4* __restrict__ anc, const float4* __restrict__ gts,
    int m, float* __restrict__ out, unsigned long long* __restrict__ gtop)
{
    __shared__ float4 sgc[MAXM];
    __shared__ float sga[MAXM];
    __shared__ int sgi[MAXM];
    __shared__ unsigned long long smax[MAXM];       // per-gt ungated max (local)
    __shared__ unsigned long long scas[MAXM * 3];   // per-gt 0.1-gated top-3 (local)

    const int tid = threadIdx.x;
    const bool active_blk = blockIdx.x < g_nwork;
    if (active_blk) {
        int4 w = g_work[blockIdx.x];
        const int cell = w.x, astart = w.y, alen = w.z;
        const int cnt = g_gtcnt[cell];

        // Prologue. smax is seeded from global with a FAKE key (hi<<32|0):
        // pure monotone max -> raising the local gate is always safe, and merge
        // skips low==0. The cascade is NOT seeded (seeding can evict real keys).
        if (tid < cnt) {
            int gi = g_gtlist[cell * MAXM + tid];
            float4 G = gts[gi];
            sgc[tid] = G;
            sga[tid] = __fmul_rn(__fsub_rn(G.z, G.x), __fsub_rn(G.w, G.y));
            sgi[tid] = gi;
            smax[tid] = __ldcg(&gtop[gi * 4 + 0]) & 0xFFFFFFFF00000000ull;
        }
        for (int i = tid; i < cnt * 3; i += TPB) scas[i] = 0ull;
        __syncthreads();

        const int jmax = (alen + TPB - 1) / TPB;
        switch (jmax) {
            case 1: run_chunk<1>(anc, out, astart, alen, cnt, tid, sgc, sga, sgi, smax, scas); break;
            case 2: run_chunk<2>(anc, out, astart, alen, cnt, tid, sgc, sga, sgi, smax, scas); break;
            case 3: run_chunk<3>(anc, out, astart, alen, cnt, tid, sgc, sga, sgi, smax, scas); break;
            default: run_chunk<4>(anc, out, astart, alen, cnt, tid, sgc, sga, sgi, smax, scas); break;
        }

        // Merge real (low!=0) local slots into global tables.
        __syncthreads();
        const unsigned* gtop_hi = (const unsigned*)gtop;
        for (int i = tid; i < cnt * 4; i += TPB) {
            int g = i >> 2, slot = i & 3;
            int orig = sgi[g];
            unsigned long long v = (slot == 0) ? smax[g] : scas[g * 3 + slot - 1];
            if ((unsigned)v == 0u) continue;           // empty or seed fake
            if (slot == 0) {
                atomicMax(&gtop[orig * 4], v);
            } else {
                unsigned gm = gtop_hi[(orig * 4 + 3) * 2 + 1];
                if ((unsigned)(v >> 32) >= gm) cascade_insert(&gtop[orig * 4 + 1], v);
            }
        }
    }

    // ---- ticket: last-finishing block resolves forced claims ----
    __syncthreads();
    __threadfence();
    __shared__ unsigned old;
    if (tid == 0) old = atomicAdd(&g_tick2, 1u);
    __syncthreads();
    if (old == gridDim.x - 1) {
        // Overlay resolve arrays on dead smem.
        int* ea = (int*)scas;                 // [MAXM*3]
        int* eg = ((int*)scas) + MAXM * 3;    // [MAXM*3]
        int* win = (int*)sgc;                 // [MAXM*3]
        __shared__ int rcnt;
        if (tid == 0) rcnt = 0;
        __syncthreads();
        if (tid < m) {
            unsigned long long s0 = __ldcg(&gtop[tid * 4 + 0]);   // overall max
            unsigned long long s1 = __ldcg(&gtop[tid * 4 + 2]);   // vals[1] (>0.1)
            unsigned long long s2 = __ldcg(&gtop[tid * 4 + 3]);   // vals[2] (>0.1)
            float v0 = __uint_as_float((unsigned)(s0 >> 32));
            float v1 = __uint_as_float((unsigned)(s1 >> 32));
            float v2 = __uint_as_float((unsigned)(s2 >> 32));
            int npos = (v0 > 0.5f) + (v1 > 0.5f) + (v2 > 0.5f);
            bool low = npos < 3;
            // k==0 always claims; empty slot = all-zero row -> ref rank0 = anchor 0.
            int a0 = s0 ? (int)(~(unsigned)s0) : 0;
            int e = atomicAdd(&rcnt, 1); ea[e] = a0; eg[e] = tid;
            if (low) {
                if (s1) { e = atomicAdd(&rcnt, 1); ea[e] = (int)(~(unsigned)s1); eg[e] = tid; }
                if (s2) { e = atomicAdd(&rcnt, 1); ea[e] = (int)(~(unsigned)s2); eg[e] = tid; }
            }
        }
        __syncthreads();
        const int E = rcnt;
        for (int j = tid; j < E; j += TPB) win[j] = -1;
        __syncthreads();
        // winner per anchor = max claiming gt (reference scatter-max), keyed on
        // the first list occurrence of each anchor.
        for (int j = tid; j < E; j += TPB) {
            int aj = ea[j];
            int rep = j;
            for (int k = 0; k < j; k++)
                if (ea[k] == aj) { rep = k; break; }
            atomicMax(&win[rep], eg[j]);
        }
        __syncthreads();
        for (int j = tid; j < E; j += TPB)
            if (win[j] >= 0) out[ea[j]] = (float)win[j];
        if (tid == 0) g_tick2 = 0;
    }
}

extern "C" void kernel_launch(void* const* d_in, const int* in_sizes, int n_in,
                              void* d_out, int out_size)
{
    const float4* anc = (const float4*)d_in[0];
    const float4* gts = (const float4*)d_in[1];
    int n = in_sizes[0] / 4;
    int m = in_sizes[1] / 4;
    float* out = (float*)d_out;

    void* ptop = nullptr;
    cudaGetSymbolAddress(&ptop, g_top);

    int nb = (n + CHUNK - 1) / CHUNK;
    k_hist<<<nb, TPB>>>(anc, n);
    k_phase2<<<NCELL * 2, TPB>>>(nb, gts, m);
    k_scatter<<<nb, TPB>>>(n, nb);
    // Worst-case chunk count: min chunk 256 anchors -> n/256 + NCELL slack.
    int mblocks = NCELL + (n + 255) / 256 + 2;
    k_main<<<mblocks, TPB>>>(anc, gts, m, out, (unsigned long long*)ptop);
}